// round 11
// baseline (speedup 1.0000x reference)
#include <cuda_runtime.h>
#include <cuda_bf16.h>
#include <cstdint>

#define BB 2
#define GG 2048
#define HH 4
#define EE 128

#define TQ 16      // q rows per block
#define TP 64      // p columns per tile
#define PSPLIT 2   // p-range splits
#define PRANGE (GG / PSPLIT)      // 1024
#define NTILE (PRANGE / TP)       // 16
#define NT 256     // threads per attn block (8 warps)

// ---------------- device scratch ----------------
__device__ float g_Q[BB * GG * 128];      // [b][g][h*32+k]
__device__ float g_K[BB * GG * 128];      // [b][g][h*32+k]
__device__ float g_Vt[BB * 128 * GG];     // transposed: [b][h*32+v][g]
__device__ float g_pacc[PSPLIT][BB * GG * 128];  // unnormalized AV partials
__device__ float g_pm[PSPLIT][BB * GG * 4];      // running max per (row,h)
__device__ float g_pl[PSPLIT][BB * GG * 4];      // softmax denom partial

// ---------------- f32x2 helpers ----------------
__device__ __forceinline__ unsigned long long pack2(float a, float b) {
    unsigned long long r;
    asm("mov.b64 %0, {%1, %2};" : "=l"(r) : "f"(a), "f"(b));
    return r;
}
__device__ __forceinline__ void unpack2(unsigned long long v, float& a, float& b) {
    asm("mov.b64 {%0, %1}, %2;" : "=f"(a), "=f"(b) : "l"(v));
}
__device__ __forceinline__ void fma2(unsigned long long& d,
                                     unsigned long long a, unsigned long long b) {
    asm("fma.rn.f32x2 %0, %1, %2, %0;" : "+l"(d) : "l"(a), "l"(b));
}
__device__ __forceinline__ void mul2(unsigned long long& d, unsigned long long a) {
    asm("mul.rn.f32x2 %0, %0, %1;" : "+l"(d) : "l"(a));
}

#define CP_ASYNC16(dst, src) \
    asm volatile("cp.async.cg.shared.global [%0], [%1], 16;" :: "r"(dst), "l"(src))
#define CP_COMMIT() asm volatile("cp.async.commit_group;" ::: "memory")
#define CP_WAIT0()  asm volatile("cp.async.wait_group 0;" ::: "memory")

// =============================================================================
// K0: fused QKV projection (round-9 version: 41us). V written transposed.
// grid = 512 blocks x 8 rows, 256 threads; d-loop unrolled x4.
// =============================================================================
__global__ __launch_bounds__(256)
void qkv_kernel(const float* __restrict__ hin,
                const float* __restrict__ Wq,
                const float* __restrict__ Wk,
                const float* __restrict__ Wv)
{
    __shared__ float hs[8 * 128];
    const int tid  = threadIdx.x;
    const int row0 = blockIdx.x * 8;

    for (int i = tid; i < 8 * 128; i += 256)
        hs[i] = hin[(size_t)row0 * 128 + i];
    __syncthreads();

    const int sub   = tid >> 7;       // 0/1 -> rows 0-3 / 4-7
    const int col   = tid & 127;
    const int rbase = sub * 4;

    float aq[4], ak[4], av[4];
#pragma unroll
    for (int r = 0; r < 4; r++) { aq[r] = 0.f; ak[r] = 0.f; av[r] = 0.f; }

    const int hh = col >> 5, k = col & 31;
    const float* wqp = Wq + hh * 128 * 32 + k;
    const float* wkp = Wk + hh * 128 * 32 + k;
    const float* wvp = Wv + hh * 128 * 32 + k;

    for (int d = 0; d < 128; d += 4) {
        float wq[4], wk4[4], wv[4];
#pragma unroll
        for (int u = 0; u < 4; u++) {
            wq[u]  = __ldg(wqp + (d + u) * 32);
            wk4[u] = __ldg(wkp + (d + u) * 32);
            wv[u]  = __ldg(wvp + (d + u) * 32);
        }
#pragma unroll
        for (int u = 0; u < 4; u++) {
#pragma unroll
            for (int r = 0; r < 4; r++) {
                const float hv = hs[(rbase + r) * 128 + d + u];
                aq[r] += hv * wq[u];
                ak[r] += hv * wk4[u];
                av[r] += hv * wv[u];
            }
        }
    }

    const int growbase = row0 + rbase;
    const int b = growbase >> 11;
#pragma unroll
    for (int r = 0; r < 4; r++) {
        const int grow = growbase + r;
        const int g    = grow & 2047;
        g_Q[(size_t)grow * 128 + col] = aq[r];
        g_K[(size_t)grow * 128 + col] = ak[r];
        g_Vt[((size_t)(b * 128 + col)) * 2048 + g] = av[r];
    }
}

// =============================================================================
// K1: head-specialized 3-phase attn tile loop.
//   phase S (scores): warp = (head, q-half): per-lane K LDS only for its head
//   phase M (MLP+softmax): warp = 2 q rows (state warp-local)
//   phase A (AV): warp = (head, q-half): per-lane V LDS only for its head
// Score/exp-weight exchange through SS smem buffer (16 KB).
// smem = 94,560 B -> 2 blocks/SM.
// =============================================================================
#define SM_QS 0                 /* 16 x 132 = 2112 */
#define SM_K  2112              /* 64 x 132 = 8448 */
#define SM_V  10560             /* 128 x 68 = 8704 */
#define SM_SS 19264             /* 16q x 4h x 64p = 4096 */
#define SM_WT 23360             /* 108 ull = 216 */
#define SM_CS 23576             /* 16q x 4h corr = 64 */
#define SMEM_FLOATS 23640
#define SMEM_BYTES (SMEM_FLOATS * 4)

__device__ __forceinline__ void mlp8(const unsigned long long* __restrict__ wtU,
                                     const float* s0v, const float* s1v,
                                     const unsigned long long* o2,
                                     float* y0, float* y1)
{
    unsigned long long x2[8];
#pragma unroll
    for (int h = 0; h < 4; h++) {
        x2[h]     = pack2(s0v[h], s1v[h]);
        x2[4 + h] = o2[h];
    }
    unsigned long long hid[8];
#pragma unroll
    for (int j = 0; j < 8; j++) {
        unsigned long long z = wtU[64 + j];
#pragma unroll
        for (int i = 0; i < 8; i++) fma2(z, wtU[j * 8 + i], x2[i]);
        float zl, zh; unpack2(z, zl, zh);
        hid[j] = pack2(fmaxf(zl, 0.f), fmaxf(zh, 0.f));
    }
#pragma unroll
    for (int h = 0; h < 4; h++) {
        unsigned long long z = wtU[104 + h];
#pragma unroll
        for (int j = 0; j < 8; j++) fma2(z, wtU[72 + h * 8 + j], hid[j]);
        unpack2(z, y0[h], y1[h]);
    }
}

__global__ __launch_bounds__(NT, 2)
void attn_kernel(const float* __restrict__ osa,
                 const float* __restrict__ w1,
                 const float* __restrict__ b1,
                 const float* __restrict__ w2,
                 const float* __restrict__ b2,
                 float* __restrict__ osaCopy,
                 int doCopy)
{
    extern __shared__ float sm[];
    const uint32_t smaddr = (uint32_t)__cvta_generic_to_shared(sm);

    float* Qs = sm + SM_QS;
    float* cs = sm + SM_CS;
    unsigned long long* wtU = (unsigned long long*)(sm + SM_WT);
    unsigned long long* ssU = (unsigned long long*)(sm + SM_SS);

    const int tid  = threadIdx.x;
    const int warp = tid >> 5;
    const int lane = tid & 31;
    const int b    = blockIdx.y;
    const int ps   = blockIdx.z;
    const int q0   = blockIdx.x * TQ;
    const int p00  = ps * PRANGE;

    const int sh  = warp & 3;      // head owned in phases S/A
    const int qh  = warp >> 2;     // q-half owned in phases S/A
    const int q0w = qh * 8;        // local q base for phases S/A
    const int qm  = warp * 2;      // local q base for phase M (2 rows)

    if (tid < 108) {
        float v;
        if (tid < 64)       v = __ldg(w1 + tid);
        else if (tid < 72)  v = __ldg(b1 + tid - 64);
        else if (tid < 104) v = __ldg(w2 + tid - 72);
        else                v = __ldg(b2 + tid - 104);
        wtU[tid] = pack2(v, v);
    }

    // Q tile: 16 rows x 128 floats, stride 132
#pragma unroll
    for (int j = 0; j < 2; j++) {
        const int c  = tid + j * 256;
        const int r  = c >> 5;
        const int cg = c & 31;
        ((float4*)(Qs + r * 132))[cg] =
            __ldg((const float4*)(g_Q + (size_t)(b * GG + q0 + r) * 132 / 132 * 128) + cg);
    }

    unsigned long long acc[8];      // AV state: (head sh, 8 local q), lane = v
    float m[2][4], lln[2][4];       // softmax state: (2 local q of phase M) x 4h
#pragma unroll
    for (int q = 0; q < 8; q++) acc[q] = 0ULL;
#pragma unroll
    for (int s = 0; s < 2; s++)
#pragma unroll
        for (int h = 0; h < 4; h++) { m[s][h] = -1e30f; lln[s][h] = 0.f; }

    for (int pt = 0; pt < NTILE; pt++) {
        const int pg0 = p00 + pt * TP;

        // ---- osa prefetch for phase-M rows (in flight across staging) ----
        unsigned long long o2[2][4];
#pragma unroll
        for (int s = 0; s < 2; s++) {
            const int qg = q0 + qm + s;
#pragma unroll
            for (int h = 0; h < 4; h++) {
                const size_t idx = ((size_t)(h * BB + b) * GG + qg) * GG + pg0 + 2 * lane;
                o2[s][h] = __ldcs((const unsigned long long*)(osa + idx));
            }
        }

        __syncthreads();   // prev tile fully consumed (SS, K, V free)

        // ---- stage K (row-permuted: row p -> (p>>1)+(p&1)*32) and Vt ----
#pragma unroll
        for (int j = 0; j < 8; j++) {
            const int c  = tid + j * 256;         // 0..2047
            const int kr = c >> 5;
            const int kc = (c & 31) * 4;
            const int pr = (kr >> 1) + ((kr & 1) << 5);
            CP_ASYNC16(smaddr + (uint32_t)(SM_K + pr * 132 + kc) * 4u,
                       g_K + ((size_t)(b * GG + pg0 + kr)) * 128 + kc);
            const int vd = c >> 4;
            const int vo = (c & 15) * 4;
            CP_ASYNC16(smaddr + (uint32_t)(SM_V + vd * 68 + vo) * 4u,
                       g_Vt + ((size_t)(b * 128 + vd)) * 2048 + pg0 + vo);
        }
        CP_COMMIT();
        CP_WAIT0();
        __syncthreads();   // tile visible

        const float* Ks = sm + SM_K;
        const float* Vt = sm + SM_V;

        // ================= phase S: scores for (head sh, 8 q rows) =========
        // lane p-pair: p0=2lane (smem row lane), p1=2lane+1 (smem row lane+32)
        {
            const ulonglong2* kR0 = (const ulonglong2*)(Ks + lane * 132 + sh * 32);
            const ulonglong2* kR1 = (const ulonglong2*)(Ks + (lane + 32) * 132 + sh * 32);
            unsigned long long sA[8], sB[8];
#pragma unroll
            for (int q = 0; q < 8; q++) { sA[q] = 0ULL; sB[q] = 0ULL; }

#pragma unroll
            for (int half = 0; half < 2; half++) {
                ulonglong2 kA[4], kB[4];
#pragma unroll
                for (int u = 0; u < 4; u++) {
                    kA[u] = kR0[half * 4 + u];
                    kB[u] = kR1[half * 4 + u];
                }
#pragma unroll
                for (int q = 0; q < 8; q++) {
                    const ulonglong2* qp =
                        (const ulonglong2*)(Qs + (q0w + q) * 132 + sh * 32) + half * 4;
#pragma unroll
                    for (int u = 0; u < 4; u++) {
                        const ulonglong2 qv = qp[u];   // broadcast
                        fma2(sA[q], qv.x, kA[u].x); fma2(sA[q], qv.y, kA[u].y);
                        fma2(sB[q], qv.x, kB[u].x); fma2(sB[q], qv.y, kB[u].y);
                    }
                }
            }
#pragma unroll
            for (int q = 0; q < 8; q++) {
                float xa, ya, xb, yb;
                unpack2(sA[q], xa, ya);
                unpack2(sB[q], xb, yb);
                ssU[((q0w + q) * 4 + sh) * 32 + lane] = pack2(xa + ya, xb + yb);
            }
        }

        // ---- osa pass-through (independent of phases) ----
        if (doCopy) {
#pragma unroll
            for (int s = 0; s < 2; s++) {
                const int qg = q0 + qm + s;
#pragma unroll
                for (int h = 0; h < 4; h++) {
                    const size_t idx = ((size_t)(h * BB + b) * GG + qg) * GG + pg0 + 2 * lane;
                    __stcs((unsigned long long*)(osaCopy + idx), o2[s][h]);
                }
            }
        }

        __syncthreads();   // scores visible to phase M

        // ================= phase M: MLP + softmax for 2 q rows ==============
#pragma unroll
        for (int s = 0; s < 2; s++) {
            const int qi = qm + s;
            float s0v[4], s1v[4];
#pragma unroll
            for (int h = 0; h < 4; h++) {
                float xa, xb;
                unpack2(ssU[(qi * 4 + h) * 32 + lane], xa, xb);
                s0v[h] = xa; s1v[h] = xb;
            }
            float y0[4], y1[4];
            mlp8(wtU, s0v, s1v, o2[s], y0, y1);

#pragma unroll
            for (int h = 0; h < 4; h++) {
                float t = fmaxf(y0[h], y1[h]);
#pragma unroll
                for (int off = 16; off; off >>= 1)
                    t = fmaxf(t, __shfl_xor_sync(0xffffffffu, t, off));
                const float mn   = fmaxf(m[s][h], t);
                const float corr = __expf(m[s][h] - mn);
                m[s][h] = mn;
                const float wa = __expf(y0[h] - mn);
                const float wb = __expf(y1[h] - mn);
                lln[s][h] = lln[s][h] * corr + wa + wb;
                ssU[(qi * 4 + h) * 32 + lane] = pack2(wa, wb);
                if (lane == 0) cs[qi * 4 + h] = corr;
            }
        }

        __syncthreads();   // exp-weights + corr visible to phase A

        // ================= phase A: AV for (head sh, 8 q rows), lane = v ====
        {
            const ulonglong2* vR = (const ulonglong2*)(Vt + (sh * 32 + lane) * 68);
#pragma unroll
            for (int q = 0; q < 8; q++) {
                const float c = cs[(q0w + q) * 4 + sh];   // broadcast
                mul2(acc[q], pack2(c, c));
            }
#pragma unroll
            for (int jg = 0; jg < 16; jg++) {
                const ulonglong2 v2 = vR[jg];
#pragma unroll
                for (int q = 0; q < 8; q++) {
                    const ulonglong2 w2 =
                        ((const ulonglong2*)(ssU + ((q0w + q) * 4 + sh) * 32))[jg]; // bcast
                    fma2(acc[q], w2.x, v2.x);
                    fma2(acc[q], w2.y, v2.y);
                }
            }
        }
    }

    // ---- epilogue ----
    // phase-M state: (m, l) for 2 q rows
#pragma unroll
    for (int s = 0; s < 2; s++) {
        const int row = b * GG + q0 + qm + s;
#pragma unroll
        for (int h = 0; h < 4; h++) {
            float ls = lln[s][h];
#pragma unroll
            for (int off = 16; off; off >>= 1)
                ls += __shfl_xor_sync(0xffffffffu, ls, off);
            if (lane == 0) {
                g_pm[ps][row * 4 + h] = m[s][h];
                g_pl[ps][row * 4 + h] = ls;
            }
        }
    }
    // phase-A state: unnormalized AV partials for (head sh, 8 q rows)
#pragma unroll
    for (int q = 0; q < 8; q++) {
        const int row = b * GG + q0 + q0w + q;
        float x, y; unpack2(acc[q], x, y);
        g_pacc[ps][(size_t)row * 128 + sh * 32 + lane] = x + y;
    }
}

// =============================================================================
// K2: combine p-split partials + output projection (round-9 version).
// =============================================================================
__global__ __launch_bounds__(128)
void outproj_kernel(const float* __restrict__ Wout,
                    float* __restrict__ out)
{
    __shared__ float hs[8 * 128];
    __shared__ float fc[8][4][PSPLIT];
    const int tid  = threadIdx.x;
    const int row0 = blockIdx.x * 8;

    if (tid < 32) {
        const int r = tid >> 2, h = tid & 3;
        const int idx = (row0 + r) * 4 + h;
        float mm[PSPLIT], ll[PSPLIT];
        float M = -1e30f;
#pragma unroll
        for (int p = 0; p < PSPLIT; p++) {
            mm[p] = g_pm[p][idx];
            ll[p] = g_pl[p][idx];
            M = fmaxf(M, mm[p]);
        }
        float L = 0.f, e[PSPLIT];
#pragma unroll
        for (int p = 0; p < PSPLIT; p++) {
            e[p] = __expf(mm[p] - M);
            L += ll[p] * e[p];
        }
#pragma unroll
        for (int p = 0; p < PSPLIT; p++) fc[r][h][p] = e[p] / L;
    }
    __syncthreads();

    for (int i = tid; i < 8 * 128; i += 128) {
        const int r = i >> 7, c = i & 127, h = c >> 5;
        float v = 0.f;
#pragma unroll
        for (int p = 0; p < PSPLIT; p++)
            v += g_pacc[p][(size_t)(row0 + r) * 128 + c] * fc[r][h][p];
        hs[i] = v;
    }
    __syncthreads();

    float a[8];
#pragma unroll
    for (int r = 0; r < 8; r++) a[r] = 0.f;

    for (int t = 0; t < 128; t += 4) {
        float w[4];
#pragma unroll
        for (int u = 0; u < 4; u++) w[u] = __ldg(Wout + (t + u) * 128 + tid);
#pragma unroll
        for (int u = 0; u < 4; u++)
#pragma unroll
            for (int r = 0; r < 8; r++) a[r] += hs[r * 128 + t + u] * w[u];
    }
#pragma unroll
    for (int r = 0; r < 8; r++)
        out[(size_t)(row0 + r) * 128 + tid] = a[r];
}

// =============================================================================
extern "C" void kernel_launch(void* const* d_in, const int* in_sizes, int n_in,
                              void* d_out, int out_size)
{
    const float* hin  = (const float*)d_in[0];
    const float* osa  = (const float*)d_in[1];
    const float* Wq   = (const float*)d_in[2];
    const float* Wk   = (const float*)d_in[3];
    const float* Wv   = (const float*)d_in[4];
    const float* Wout = (const float*)d_in[5];
    const float* w1   = (const float*)d_in[6];
    const float* b1   = (const float*)d_in[7];
    const float* w2   = (const float*)d_in[8];
    const float* b2   = (const float*)d_in[9];
    (void)in_sizes; (void)n_in;

    float* out = (float*)d_out;

    const int OUT_ELEMS = BB * GG * EE;
    const long long OSA_ELEMS = (long long)HH * BB * GG * GG;
    const int doCopy = ((long long)out_size >= OUT_ELEMS + OSA_ELEMS) ? 1 : 0;
    float* osaCopy = doCopy ? (out + OUT_ELEMS) : out;

    cudaFuncSetAttribute(attn_kernel,
                         cudaFuncAttributeMaxDynamicSharedMemorySize, SMEM_BYTES);

    qkv_kernel<<<BB * GG / 8, 256>>>(hin, Wq, Wk, Wv);
    attn_kernel<<<dim3(GG / TQ, BB, PSPLIT), NT, SMEM_BYTES>>>(
        osa, w1, b1, w2, b2, osaCopy, doCopy);
    outproj_kernel<<<BB * GG / 8, 128>>>(Wout, out);
}

// round 12
// speedup vs baseline: 1.5350x; 1.5350x over previous
#include <cuda_runtime.h>
#include <cuda_bf16.h>
#include <cstdint>

#define BB 2
#define GG 2048
#define HH 4
#define EE 128

#define TQ 32      // q rows per block (16 warps x 2 q-rows)
#define TP 64      // p columns per tile
#define PSPLIT 2   // p-range splits
#define PRANGE (GG / PSPLIT)      // 1024
#define NTILE (PRANGE / TP)       // 16
#define NT 512     // threads per attn block (16 warps)

// ---------------- device scratch ----------------
__device__ float g_Q[BB * GG * 128];      // [b][g][h*32+k]
__device__ float g_K[BB * GG * 128];      // [b][g][h*32+k]
__device__ float g_Vt[BB * 128 * GG];     // transposed: [b][h*32+v][g]
__device__ float g_pacc[PSPLIT][BB * GG * 128];  // unnormalized AV partials
__device__ float g_pm[PSPLIT][BB * GG * 4];      // running max per (row,h)
__device__ float g_pl[PSPLIT][BB * GG * 4];      // softmax denom partial

// ---------------- f32x2 helpers ----------------
__device__ __forceinline__ unsigned long long pack2(float a, float b) {
    unsigned long long r;
    asm("mov.b64 %0, {%1, %2};" : "=l"(r) : "f"(a), "f"(b));
    return r;
}
__device__ __forceinline__ void unpack2(unsigned long long v, float& a, float& b) {
    asm("mov.b64 {%0, %1}, %2;" : "=f"(a), "=f"(b) : "l"(v));
}
__device__ __forceinline__ void fma2(unsigned long long& d,
                                     unsigned long long a, unsigned long long b) {
    asm("fma.rn.f32x2 %0, %1, %2, %0;" : "+l"(d) : "l"(a), "l"(b));
}
__device__ __forceinline__ void mul2(unsigned long long& d, unsigned long long a) {
    asm("mul.rn.f32x2 %0, %0, %1;" : "+l"(d) : "l"(a));
}

#define CP_ASYNC16(dst, src) \
    asm volatile("cp.async.cg.shared.global [%0], [%1], 16;" :: "r"(dst), "l"(src))
#define CP_COMMIT() asm volatile("cp.async.commit_group;" ::: "memory")
#define CP_WAIT0()  asm volatile("cp.async.wait_group 0;" ::: "memory")

// =============================================================================
// K0: fused QKV projection (round-9 version, known 41us). V written transposed.
// =============================================================================
__global__ __launch_bounds__(256)
void qkv_kernel(const float* __restrict__ hin,
                const float* __restrict__ Wq,
                const float* __restrict__ Wk,
                const float* __restrict__ Wv)
{
    __shared__ float hs[8 * 128];
    const int tid  = threadIdx.x;
    const int row0 = blockIdx.x * 8;

    for (int i = tid; i < 8 * 128; i += 256)
        hs[i] = hin[(size_t)row0 * 128 + i];
    __syncthreads();

    const int sub   = tid >> 7;
    const int col   = tid & 127;
    const int rbase = sub * 4;

    float aq[4], ak[4], av[4];
#pragma unroll
    for (int r = 0; r < 4; r++) { aq[r] = 0.f; ak[r] = 0.f; av[r] = 0.f; }

    const int hh = col >> 5, k = col & 31;
    const float* wqp = Wq + hh * 128 * 32 + k;
    const float* wkp = Wk + hh * 128 * 32 + k;
    const float* wvp = Wv + hh * 128 * 32 + k;

    for (int d = 0; d < 128; d += 4) {
        float wq[4], wk4[4], wv[4];
#pragma unroll
        for (int u = 0; u < 4; u++) {
            wq[u]  = __ldg(wqp + (d + u) * 32);
            wk4[u] = __ldg(wkp + (d + u) * 32);
            wv[u]  = __ldg(wvp + (d + u) * 32);
        }
#pragma unroll
        for (int u = 0; u < 4; u++) {
#pragma unroll
            for (int r = 0; r < 4; r++) {
                const float hv = hs[(rbase + r) * 128 + d + u];
                aq[r] += hv * wq[u];
                ak[r] += hv * wk4[u];
                av[r] += hv * wv[u];
            }
        }
    }

    const int growbase = row0 + rbase;
    const int b = growbase >> 11;
#pragma unroll
    for (int r = 0; r < 4; r++) {
        const int grow = growbase + r;
        const int g    = grow & 2047;
        g_Q[(size_t)grow * 128 + col] = aq[r];
        g_K[(size_t)grow * 128 + col] = ak[r];
        g_Vt[((size_t)(b * 128 + col)) * 2048 + g] = av[r];
    }
}

// =============================================================================
// K1: round-9 warp-level compute, new single-barrier double-buffered pipeline.
// grid = (64 qtiles, 2 batch, 2 psplit) = 256 blocks, 512 thr = 16 warps.
// Warp owns 2 q rows; lane owns p-pair (2*lane, 2*lane+1).
// Per tile: wait_group 0 -> ONE __syncthreads -> issue cp.async for t+1 ->
// compute tile t (staging fully overlapped with compute).
// smem = 187,744 B -> 1 block/SM (16 warps = 4/SMSP).
// =============================================================================
#define SM_QS 0                 /* 32 x 132       = 4224  */
#define SM_K  4224              /* 2 x 64 x 132   = 16896 */
#define SM_V  21120             /* 2 x 128 x 68   = 17408 */
#define SM_WS 38528             /* 16 warps x 512 = 8192  */
#define SM_WT 46720             /* 108 ull        = 216   */
#define SMEM_FLOATS 46936
#define SMEM_BYTES (SMEM_FLOATS * 4)
#define KBUF 8448
#define VBUF 8704

__device__ __forceinline__ void stage_cp(uint32_t smaddr, int buf, int b,
                                         int pg0, int tid)
{
#pragma unroll
    for (int j = 0; j < 4; j++) {
        const int c  = tid + j * 512;             // 0..2047
        // K: 64 rows x 32 chunks; row p -> smem row (p>>1)+(p&1)*32
        const int kr = c >> 5;
        const int kc = (c & 31) * 4;
        const int pr = (kr >> 1) + ((kr & 1) << 5);
        CP_ASYNC16(smaddr + (uint32_t)(SM_K + buf * KBUF + pr * 132 + kc) * 4u,
                   g_K + ((size_t)(b * GG + pg0 + kr)) * 128 + kc);
        // V: 128 rows x 16 chunks (d-major)
        const int vd = c >> 4;
        const int vo = (c & 15) * 4;
        CP_ASYNC16(smaddr + (uint32_t)(SM_V + buf * VBUF + vd * 68 + vo) * 4u,
                   g_Vt + ((size_t)(b * 128 + vd)) * 2048 + pg0 + vo);
    }
}

__device__ __forceinline__ void mlp8(const unsigned long long* __restrict__ wtU,
                                     const float* s0v, const float* s1v,
                                     const unsigned long long* o2,
                                     float* y0, float* y1)
{
    unsigned long long x2[8];
#pragma unroll
    for (int h = 0; h < 4; h++) {
        x2[h]     = pack2(s0v[h], s1v[h]);
        x2[4 + h] = o2[h];
    }
    unsigned long long hid[8];
#pragma unroll
    for (int j = 0; j < 8; j++) {
        unsigned long long z = wtU[64 + j];
#pragma unroll
        for (int i = 0; i < 8; i++) fma2(z, wtU[j * 8 + i], x2[i]);
        float zl, zh; unpack2(z, zl, zh);
        hid[j] = pack2(fmaxf(zl, 0.f), fmaxf(zh, 0.f));
    }
#pragma unroll
    for (int h = 0; h < 4; h++) {
        unsigned long long z = wtU[104 + h];
#pragma unroll
        for (int j = 0; j < 8; j++) fma2(z, wtU[72 + h * 8 + j], hid[j]);
        unpack2(z, y0[h], y1[h]);
    }
}

__global__ __launch_bounds__(NT, 1)
void attn_kernel(const float* __restrict__ osa,
                 const float* __restrict__ w1,
                 const float* __restrict__ b1,
                 const float* __restrict__ w2,
                 const float* __restrict__ b2,
                 float* __restrict__ osaCopy,
                 int doCopy)
{
    extern __shared__ float sm[];
    const uint32_t smaddr = (uint32_t)__cvta_generic_to_shared(sm);

    float* Qs = sm + SM_QS;
    unsigned long long* wtU = (unsigned long long*)(sm + SM_WT);

    const int tid  = threadIdx.x;
    const int warp = tid >> 5;
    const int lane = tid & 31;
    const int b    = blockIdx.y;
    const int ps   = blockIdx.z;
    const int q0   = blockIdx.x * TQ;
    const int qw   = warp * 2;
    const int p00  = ps * PRANGE;

    unsigned long long* wsU = (unsigned long long*)(sm + SM_WS) + warp * 256;

    if (tid < 108) {
        float v;
        if (tid < 64)       v = __ldg(w1 + tid);
        else if (tid < 72)  v = __ldg(b1 + tid - 64);
        else if (tid < 104) v = __ldg(w2 + tid - 72);
        else                v = __ldg(b2 + tid - 104);
        wtU[tid] = pack2(v, v);
    }

    // Q tile: 32 rows x 128 floats, stride 132 (1024 float4 / 512 thr)
#pragma unroll
    for (int j = 0; j < 2; j++) {
        const int c  = tid + j * 512;
        const int r  = c >> 5;
        const int cg = c & 31;
        ((float4*)(Qs + r * 132))[cg] =
            __ldg((const float4*)(g_Q + (size_t)(b * GG + q0 + r) * 128) + cg);
    }

    // prologue: stage tile 0
    stage_cp(smaddr, 0, b, p00, tid);
    CP_COMMIT();

    unsigned long long acc[2][4];
    float m[2][4], lln[2][4];
#pragma unroll
    for (int q = 0; q < 2; q++)
#pragma unroll
        for (int h = 0; h < 4; h++) { acc[q][h] = 0ULL; m[q][h] = -1e30f; lln[q][h] = 0.f; }

    for (int pt = 0; pt < NTILE; pt++) {
        const int pg0 = p00 + pt * TP;
        const int buf = pt & 1;

        // ---- osa pair loads (LDG in flight until MLP) ----
        unsigned long long o2[2][4];
#pragma unroll
        for (int s = 0; s < 2; s++) {
            const int qg = q0 + qw + s;
#pragma unroll
            for (int h = 0; h < 4; h++) {
                const size_t idx = ((size_t)(h * BB + b) * GG + qg) * GG + pg0 + 2 * lane;
                o2[s][h] = __ldcs((const unsigned long long*)(osa + idx));
            }
        }

        // ---- single sync point per tile ----
        CP_WAIT0();        // my slice of tile pt arrived
        __syncthreads();   // everyone's slice visible + buffers of pt-1 reusable

        // ---- immediately overlap: stage tile pt+1 into other buffer ----
        if (pt + 1 < NTILE) {
            stage_cp(smaddr, buf ^ 1, b, pg0 + TP, tid);
            CP_COMMIT();
        }

        const float* Ks = sm + SM_K + buf * KBUF;
        const float* Vt = sm + SM_V + buf * VBUF;

        // ---- osa pass-through ----
        if (doCopy) {
#pragma unroll
            for (int s = 0; s < 2; s++) {
                const int qg = q0 + qw + s;
#pragma unroll
                for (int h = 0; h < 4; h++) {
                    const size_t idx = ((size_t)(h * BB + b) * GG + qg) * GG + pg0 + 2 * lane;
                    __stcs((unsigned long long*)(osaCopy + idx), o2[s][h]);
                }
            }
        }

        // ---- scores: packed over d-pairs; rows lane / lane+32 = p0 / p1 ----
        float s0[2][4], s1[2][4];
        {
            const ulonglong2* kR0 = (const ulonglong2*)(Ks + lane * 132);
            const ulonglong2* kR1 = (const ulonglong2*)(Ks + (lane + 32) * 132);
            const ulonglong2* qA  = (const ulonglong2*)(Qs + (qw + 0) * 132);
            const ulonglong2* qB  = (const ulonglong2*)(Qs + (qw + 1) * 132);
#pragma unroll
            for (int h = 0; h < 4; h++) {
                unsigned long long a00 = 0, a01 = 0, a10 = 0, a11 = 0;
#pragma unroll
                for (int u = 0; u < 8; u++) {
                    const ulonglong2 k0 = kR0[h * 8 + u];
                    const ulonglong2 k1 = kR1[h * 8 + u];
                    const ulonglong2 qa = qA[h * 8 + u];
                    const ulonglong2 qb = qB[h * 8 + u];
                    fma2(a00, qa.x, k0.x); fma2(a00, qa.y, k0.y);
                    fma2(a01, qa.x, k1.x); fma2(a01, qa.y, k1.y);
                    fma2(a10, qb.x, k0.x); fma2(a10, qb.y, k0.y);
                    fma2(a11, qb.x, k1.x); fma2(a11, qb.y, k1.y);
                }
                float x, y;
                unpack2(a00, x, y); s0[0][h] = x + y;
                unpack2(a01, x, y); s1[0][h] = x + y;
                unpack2(a10, x, y); s0[1][h] = x + y;
                unpack2(a11, x, y); s1[1][h] = x + y;
            }
        }

        // ---- MLP ----
        float y0[2][4], y1[2][4];
#pragma unroll
        for (int s = 0; s < 2; s++)
            mlp8(wtU, s0[s], s1[s], o2[s], y0[s], y1[s]);

        // ---- online softmax: ballot-gated max update, per-lane l ----
        {
            bool need = false;
#pragma unroll
            for (int s = 0; s < 2; s++)
#pragma unroll
                for (int h = 0; h < 4; h++)
                    need |= (fmaxf(y0[s][h], y1[s][h]) > m[s][h]);

            if (__ballot_sync(0xffffffffu, need)) {
#pragma unroll
                for (int s = 0; s < 2; s++) {
#pragma unroll
                    for (int h = 0; h < 4; h++) {
                        float t = fmaxf(y0[s][h], y1[s][h]);
#pragma unroll
                        for (int off = 16; off; off >>= 1)
                            t = fmaxf(t, __shfl_xor_sync(0xffffffffu, t, off));
                        if (t > m[s][h]) {            // warp-uniform
                            const float corr = __expf(m[s][h] - t);
                            lln[s][h] *= corr;
                            mul2(acc[s][h], pack2(corr, corr));
                            m[s][h] = t;
                        }
                    }
                }
            }
#pragma unroll
            for (int s = 0; s < 2; s++) {
#pragma unroll
                for (int h = 0; h < 4; h++) {
                    const float wa = __expf(y0[s][h] - m[s][h]);
                    const float wb = __expf(y1[s][h] - m[s][h]);
                    lln[s][h] += wa + wb;
                    wsU[(s * 4 + h) * 32 + lane] = pack2(wa, wb);
                }
            }
        }
        __syncwarp();

        // ---- AV: lane = v; packed over p-pairs ----
#pragma unroll
        for (int h = 0; h < 4; h++) {
            const ulonglong2* vR = (const ulonglong2*)(Vt + (h * 32 + lane) * 68);
            const ulonglong2* wA = (const ulonglong2*)(wsU + (0 * 4 + h) * 32);
            const ulonglong2* wB = (const ulonglong2*)(wsU + (1 * 4 + h) * 32);
            unsigned long long A0 = acc[0][h], A1 = acc[1][h];
#pragma unroll
            for (int jg = 0; jg < 16; jg++) {
                const ulonglong2 v2 = vR[jg];
                const ulonglong2 wa = wA[jg];
                const ulonglong2 wb = wB[jg];
                fma2(A0, wa.x, v2.x); fma2(A0, wa.y, v2.y);
                fma2(A1, wb.x, v2.x); fma2(A1, wb.y, v2.y);
            }
            acc[0][h] = A0; acc[1][h] = A1;
        }
        __syncwarp();   // ws reused next tile (per-warp)
    }

    // ---- epilogue: unnormalized partials + (m, l) ----
#pragma unroll
    for (int q = 0; q < 2; q++) {
        const int qg  = q0 + qw + q;
        const int row = b * GG + qg;
#pragma unroll
        for (int h = 0; h < 4; h++) {
            float ls = lln[q][h];
#pragma unroll
            for (int off = 16; off; off >>= 1)
                ls += __shfl_xor_sync(0xffffffffu, ls, off);
            if (lane == 0) {
                g_pm[ps][row * 4 + h] = m[q][h];
                g_pl[ps][row * 4 + h] = ls;
            }
            float x, y; unpack2(acc[q][h], x, y);
            g_pacc[ps][(size_t)row * 128 + h * 32 + lane] = x + y;
        }
    }
}

// =============================================================================
// K2: combine p-split partials + output projection (round-9 version).
// =============================================================================
__global__ __launch_bounds__(128)
void outproj_kernel(const float* __restrict__ Wout,
                    float* __restrict__ out)
{
    __shared__ float hs[8 * 128];
    __shared__ float fc[8][4][PSPLIT];
    const int tid  = threadIdx.x;
    const int row0 = blockIdx.x * 8;

    if (tid < 32) {
        const int r = tid >> 2, h = tid & 3;
        const int idx = (row0 + r) * 4 + h;
        float mm[PSPLIT], ll[PSPLIT];
        float M = -1e30f;
#pragma unroll
        for (int p = 0; p < PSPLIT; p++) {
            mm[p] = g_pm[p][idx];
            ll[p] = g_pl[p][idx];
            M = fmaxf(M, mm[p]);
        }
        float L = 0.f, e[PSPLIT];
#pragma unroll
        for (int p = 0; p < PSPLIT; p++) {
            e[p] = __expf(mm[p] - M);
            L += ll[p] * e[p];
        }
#pragma unroll
        for (int p = 0; p < PSPLIT; p++) fc[r][h][p] = e[p] / L;
    }
    __syncthreads();

    for (int i = tid; i < 8 * 128; i += 128) {
        const int r = i >> 7, c = i & 127, h = c >> 5;
        float v = 0.f;
#pragma unroll
        for (int p = 0; p < PSPLIT; p++)
            v += g_pacc[p][(size_t)(row0 + r) * 128 + c] * fc[r][h][p];
        hs[i] = v;
    }
    __syncthreads();

    float a[8];
#pragma unroll
    for (int r = 0; r < 8; r++) a[r] = 0.f;

    for (int t = 0; t < 128; t += 4) {
        float w[4];
#pragma unroll
        for (int u = 0; u < 4; u++) w[u] = __ldg(Wout + (t + u) * 128 + tid);
#pragma unroll
        for (int u = 0; u < 4; u++)
#pragma unroll
            for (int r = 0; r < 8; r++) a[r] += hs[r * 128 + t + u] * w[u];
    }
#pragma unroll
    for (int r = 0; r < 8; r++)
        out[(size_t)(row0 + r) * 128 + tid] = a[r];
}

// =============================================================================
extern "C" void kernel_launch(void* const* d_in, const int* in_sizes, int n_in,
                              void* d_out, int out_size)
{
    const float* hin  = (const float*)d_in[0];
    const float* osa  = (const float*)d_in[1];
    const float* Wq   = (const float*)d_in[2];
    const float* Wk   = (const float*)d_in[3];
    const float* Wv   = (const float*)d_in[4];
    const float* Wout = (const float*)d_in[5];
    const float* w1   = (const float*)d_in[6];
    const float* b1   = (const float*)d_in[7];
    const float* w2   = (const float*)d_in[8];
    const float* b2   = (const float*)d_in[9];
    (void)in_sizes; (void)n_in;

    float* out = (float*)d_out;

    const int OUT_ELEMS = BB * GG * EE;
    const long long OSA_ELEMS = (long long)HH * BB * GG * GG;
    const int doCopy = ((long long)out_size >= OUT_ELEMS + OSA_ELEMS) ? 1 : 0;
    float* osaCopy = doCopy ? (out + OUT_ELEMS) : out;

    cudaFuncSetAttribute(attn_kernel,
                         cudaFuncAttributeMaxDynamicSharedMemorySize, SMEM_BYTES);

    qkv_kernel<<<BB * GG / 8, 256>>>(hin, Wq, Wk, Wv);
    attn_kernel<<<dim3(GG / TQ, BB, PSPLIT), NT, SMEM_BYTES>>>(
        osa, w1, b1, w2, b2, osaCopy, doCopy);
    outproj_kernel<<<BB * GG / 8, 128>>>(Wout, out);
}

// round 13
// speedup vs baseline: 1.6847x; 1.0975x over previous
#include <cuda_runtime.h>
#include <cuda_bf16.h>
#include <cstdint>

#define BB 2
#define GG 2048
#define HH 4
#define EE 128

#define TQ 64      // q rows per block (16 warps x 4 q-rows)
#define TP 32      // p columns per tile (lane = p)
#define PSPLIT 2
#define PRANGE (GG / PSPLIT)      // 1024
#define NTILE (PRANGE / TP)       // 32
#define NT 512     // 16 warps

// ---------------- device scratch ----------------
__device__ float          g_Q[BB * GG * 128];     // [b][g][h*32+k]
__device__ float          g_K[BB * GG * 128];     // [b][g][h*32+k]
__device__ __nv_bfloat16  g_Vt[BB * 128 * GG];    // transposed bf16: [b][h*32+v][g]
__device__ float g_pacc[PSPLIT][BB * GG * 128];
__device__ float g_pm[PSPLIT][BB * GG * 4];
__device__ float g_pl[PSPLIT][BB * GG * 4];

// ---------------- f32x2 helpers ----------------
__device__ __forceinline__ unsigned long long pack2(float a, float b) {
    unsigned long long r;
    asm("mov.b64 %0, {%1, %2};" : "=l"(r) : "f"(a), "f"(b));
    return r;
}
__device__ __forceinline__ void unpack2(unsigned long long v, float& a, float& b) {
    asm("mov.b64 {%0, %1}, %2;" : "=f"(a), "=f"(b) : "l"(v));
}
__device__ __forceinline__ void fma2(unsigned long long& d,
                                     unsigned long long a, unsigned long long b) {
    asm("fma.rn.f32x2 %0, %1, %2, %0;" : "+l"(d) : "l"(a), "l"(b));
}
__device__ __forceinline__ void mul2(unsigned long long& d, unsigned long long a) {
    asm("mul.rn.f32x2 %0, %0, %1;" : "+l"(d) : "l"(a));
}
__device__ __forceinline__ void add2(unsigned long long& d, unsigned long long a) {
    asm("add.rn.f32x2 %0, %0, %1;" : "+l"(d) : "l"(a));
}

#define CP_ASYNC16(dst, src) \
    asm volatile("cp.async.cg.shared.global [%0], [%1], 16;" :: "r"(dst), "l"(src))
#define CP_COMMIT() asm volatile("cp.async.commit_group;" ::: "memory")
#define CP_WAIT0()  asm volatile("cp.async.wait_group 0;" ::: "memory")

// =============================================================================
// K0: fused QKV projection (R9 structure, V converted to bf16 + transposed).
// =============================================================================
__global__ __launch_bounds__(256)
void qkv_kernel(const float* __restrict__ hin,
                const float* __restrict__ Wq,
                const float* __restrict__ Wk,
                const float* __restrict__ Wv)
{
    __shared__ float hs[8 * 128];
    const int tid  = threadIdx.x;
    const int row0 = blockIdx.x * 8;

    for (int i = tid; i < 8 * 128; i += 256)
        hs[i] = hin[(size_t)row0 * 128 + i];
    __syncthreads();

    const int sub   = tid >> 7;
    const int col   = tid & 127;
    const int rbase = sub * 4;

    float aq[4], ak[4], av[4];
#pragma unroll
    for (int r = 0; r < 4; r++) { aq[r] = 0.f; ak[r] = 0.f; av[r] = 0.f; }

    const int hh = col >> 5, k = col & 31;
    const float* wqp = Wq + hh * 128 * 32 + k;
    const float* wkp = Wk + hh * 128 * 32 + k;
    const float* wvp = Wv + hh * 128 * 32 + k;

    for (int d = 0; d < 128; d += 4) {
        float wq[4], wk4[4], wv[4];
#pragma unroll
        for (int u = 0; u < 4; u++) {
            wq[u]  = __ldg(wqp + (d + u) * 32);
            wk4[u] = __ldg(wkp + (d + u) * 32);
            wv[u]  = __ldg(wvp + (d + u) * 32);
        }
#pragma unroll
        for (int u = 0; u < 4; u++) {
#pragma unroll
            for (int r = 0; r < 4; r++) {
                const float hv = hs[(rbase + r) * 128 + d + u];
                aq[r] += hv * wq[u];
                ak[r] += hv * wk4[u];
                av[r] += hv * wv[u];
            }
        }
    }

    const int growbase = row0 + rbase;
    const int b = growbase >> 11;
#pragma unroll
    for (int r = 0; r < 4; r++) {
        const int grow = growbase + r;
        const int g    = grow & 2047;
        g_Q[(size_t)grow * 128 + col] = aq[r];
        g_K[(size_t)grow * 128 + col] = ak[r];
        g_Vt[((size_t)(b * 128 + col)) * 2048 + g] = __float2bfloat16(av[r]);
    }
}

// =============================================================================
// K1: 4 q-rows/warp, TP=32 (lane = p), bf16 V, double-buffered single-barrier.
// grid = (32, 2, 2) = 128 blocks (single wave), 512 threads = 16 warps.
// smem = 121,696 B.
// =============================================================================
#define SM_QS 0                  /* 64 x 132          = 8448 */
#define SM_K  8448               /* 2 x 32 x 132      = 8448 */
#define SM_V  16896              /* 2 x 128 rows x 80B = 5120 */
#define SM_WS 22016              /* 16 warps x 256 ull = 8192 */
#define SM_WT 30208              /* 108 ull            = 216 */
#define SMEM_FLOATS 30424
#define SMEM_BYTES (SMEM_FLOATS * 4)
#define KBUF 4224                /* floats */
#define VBUF 2560                /* floats (128 rows x 80 bytes) */

__device__ __forceinline__ void stage_cp(uint32_t smaddr, int buf, int b,
                                         int pg0, int tid)
{
    // K tile: 32 rows x 128 floats (1024 16B chunks)
#pragma unroll
    for (int j = 0; j < 2; j++) {
        const int c  = tid + j * 512;
        const int kr = c >> 5;
        const int kc = (c & 31) * 4;
        CP_ASYNC16(smaddr + (uint32_t)(SM_K + buf * KBUF + kr * 132 + kc) * 4u,
                   g_K + ((size_t)(b * GG + pg0 + kr)) * 128 + kc);
    }
    // V tile bf16: 128 rows x 32 p x 2B = 64B/row (512 16B chunks), row stride 80B
    {
        const int vd = tid >> 2;
        const int vo = tid & 3;
        CP_ASYNC16(smaddr + (uint32_t)(SM_V + buf * VBUF) * 4u + vd * 80u + vo * 16u,
                   (const char*)g_Vt + ((size_t)(b * 128 + vd) * 2048 + pg0) * 2 + vo * 16);
    }
}

__device__ __forceinline__ void mlp8(const unsigned long long* __restrict__ wtU,
                                     const unsigned long long* x2,
                                     float* y0, float* y1)
{
    unsigned long long hid[8];
#pragma unroll
    for (int j = 0; j < 8; j++) {
        unsigned long long z = wtU[64 + j];
#pragma unroll
        for (int i = 0; i < 8; i++) fma2(z, wtU[j * 8 + i], x2[i]);
        float zl, zh; unpack2(z, zl, zh);
        hid[j] = pack2(fmaxf(zl, 0.f), fmaxf(zh, 0.f));
    }
#pragma unroll
    for (int h = 0; h < 4; h++) {
        unsigned long long z = wtU[104 + h];
#pragma unroll
        for (int j = 0; j < 8; j++) fma2(z, wtU[72 + h * 8 + j], hid[j]);
        unpack2(z, y0[h], y1[h]);
    }
}

__global__ __launch_bounds__(NT, 1)
void attn_kernel(const float* __restrict__ osa,
                 const float* __restrict__ w1,
                 const float* __restrict__ b1,
                 const float* __restrict__ w2,
                 const float* __restrict__ b2,
                 float* __restrict__ osaCopy,
                 int doCopy)
{
    extern __shared__ float sm[];
    const uint32_t smaddr = (uint32_t)__cvta_generic_to_shared(sm);

    float* Qs = sm + SM_QS;
    unsigned long long* wtU = (unsigned long long*)(sm + SM_WT);

    const int tid  = threadIdx.x;
    const int warp = tid >> 5;
    const int lane = tid & 31;
    const int b    = blockIdx.y;
    const int ps   = blockIdx.z;
    const int q0   = blockIdx.x * TQ;
    const int qw   = warp * 4;          // 4 q rows per warp
    const int p00  = ps * PRANGE;

    unsigned long long* wsU = (unsigned long long*)(sm + SM_WS) + warp * 256;

    if (tid < 108) {
        float v;
        if (tid < 64)       v = __ldg(w1 + tid);
        else if (tid < 72)  v = __ldg(b1 + tid - 64);
        else if (tid < 104) v = __ldg(w2 + tid - 72);
        else                v = __ldg(b2 + tid - 104);
        wtU[tid] = pack2(v, v);
    }

    // Q tile: 64 rows x 128 floats, stride 132 (2048 f4 chunks / 512 thr)
#pragma unroll
    for (int j = 0; j < 4; j++) {
        const int c  = tid + j * 512;
        const int r  = c >> 5;
        const int cg = c & 31;
        ((float4*)(Qs + r * 132))[cg] =
            __ldg((const float4*)(g_Q + (size_t)(b * GG + q0 + r) * 128) + cg);
    }

    // prologue: stage tile 0
    stage_cp(smaddr, 0, b, p00, tid);
    CP_COMMIT();

    unsigned long long acc[2][4];   // packed over q within pair, per h; lane = v
    unsigned long long lln[2][4];   // per-lane softmax denom, packed over q
    float m[4][4];                  // running max, warp-uniform
#pragma unroll
    for (int qp = 0; qp < 2; qp++)
#pragma unroll
        for (int h = 0; h < 4; h++) { acc[qp][h] = 0ULL; lln[qp][h] = 0ULL; }
#pragma unroll
    for (int q = 0; q < 4; q++)
#pragma unroll
        for (int h = 0; h < 4; h++) m[q][h] = -1e30f;

    for (int pt = 0; pt < NTILE; pt++) {
        const int pg0 = p00 + pt * TP;
        const int buf = pt & 1;

        // ---- osa loads: scalar per (q,h), p = lane; packed over q-pairs ----
        unsigned long long o2[2][4];
#pragma unroll
        for (int qp = 0; qp < 2; qp++) {
            const int qa = q0 + qw + 2 * qp;
#pragma unroll
            for (int h = 0; h < 4; h++) {
                const size_t base = ((size_t)(h * BB + b) * GG + qa) * GG + pg0 + lane;
                const float v0 = __ldcs(osa + base);
                const float v1 = __ldcs(osa + base + GG);
                o2[qp][h] = pack2(v0, v1);
            }
        }

        // ---- single sync point per tile ----
        CP_WAIT0();
        __syncthreads();

        if (pt + 1 < NTILE) {
            stage_cp(smaddr, buf ^ 1, b, pg0 + TP, tid);
            CP_COMMIT();
        }

        const float* Ks = sm + SM_K + buf * KBUF;
        const char*  Vs = (const char*)(sm + SM_V + buf * VBUF);

        // ---- osa pass-through ----
        if (doCopy) {
#pragma unroll
            for (int qp = 0; qp < 2; qp++) {
                const int qa = q0 + qw + 2 * qp;
#pragma unroll
                for (int h = 0; h < 4; h++) {
                    const size_t base = ((size_t)(h * BB + b) * GG + qa) * GG + pg0 + lane;
                    float v0, v1; unpack2(o2[qp][h], v0, v1);
                    __stcs((float*)osaCopy + base, v0);
                    __stcs((float*)osaCopy + base + GG, v1);
                }
            }
        }

        // ---- scores: lane = p (its K row), 4 q rows share the K reads ----
        float s[4][4];
        {
            const ulonglong2* kR = (const ulonglong2*)(Ks + lane * 132);
#pragma unroll
            for (int h = 0; h < 4; h++) {
                unsigned long long a[4];
#pragma unroll
                for (int q = 0; q < 4; q++) a[q] = 0ULL;
#pragma unroll
                for (int u = 0; u < 8; u++) {
                    const ulonglong2 kv = kR[h * 8 + u];
#pragma unroll
                    for (int q = 0; q < 4; q++) {
                        const ulonglong2 qv =
                            ((const ulonglong2*)(Qs + (qw + q) * 132))[h * 8 + u];
                        fma2(a[q], qv.x, kv.x);
                        fma2(a[q], qv.y, kv.y);
                    }
                }
#pragma unroll
                for (int q = 0; q < 4; q++) {
                    float x, y; unpack2(a[q], x, y);
                    s[q][h] = x + y;
                }
            }
        }

        // ---- MLP + softmax, two q-pair passes ----
#pragma unroll
        for (int qp = 0; qp < 2; qp++) {
            unsigned long long x2[8];
#pragma unroll
            for (int h = 0; h < 4; h++) {
                x2[h]     = pack2(s[2 * qp][h], s[2 * qp + 1][h]);
                x2[4 + h] = o2[qp][h];
            }
            float y0[4], y1[4];
            mlp8(wtU, x2, y0, y1);

            bool need = false;
#pragma unroll
            for (int h = 0; h < 4; h++)
                need |= (y0[h] > m[2 * qp][h]) | (y1[h] > m[2 * qp + 1][h]);

            if (__ballot_sync(0xffffffffu, need)) {
#pragma unroll
                for (int h = 0; h < 4; h++) {
                    float t0 = y0[h], t1 = y1[h];
#pragma unroll
                    for (int off = 16; off; off >>= 1) {
                        t0 = fmaxf(t0, __shfl_xor_sync(0xffffffffu, t0, off));
                        t1 = fmaxf(t1, __shfl_xor_sync(0xffffffffu, t1, off));
                    }
                    float c0 = 1.f, c1 = 1.f;
                    if (t0 > m[2 * qp][h])     { c0 = __expf(m[2 * qp][h] - t0);     m[2 * qp][h] = t0; }
                    if (t1 > m[2 * qp + 1][h]) { c1 = __expf(m[2 * qp + 1][h] - t1); m[2 * qp + 1][h] = t1; }
                    const unsigned long long cc = pack2(c0, c1);
                    mul2(acc[qp][h], cc);
                    mul2(lln[qp][h], cc);
                }
            }
#pragma unroll
            for (int h = 0; h < 4; h++) {
                const float wa = __expf(y0[h] - m[2 * qp][h]);
                const float wb = __expf(y1[h] - m[2 * qp + 1][h]);
                const unsigned long long w01 = pack2(wa, wb);
                add2(lln[qp][h], w01);
                wsU[(qp * 4 + h) * 32 + lane] = w01;
            }
        }
        __syncwarp();

        // ---- AV: lane = v; bf16 V row; weights broadcast from ws ----
#pragma unroll
        for (int h = 0; h < 4; h++) {
            const uint4* vR = (const uint4*)(Vs + (h * 32 + lane) * 80);
            const ulonglong2* w0 = (const ulonglong2*)(wsU + (0 * 4 + h) * 32);
            const ulonglong2* w1p = (const ulonglong2*)(wsU + (1 * 4 + h) * 32);
            unsigned long long A0 = acc[0][h], A1 = acc[1][h];
#pragma unroll
            for (int g = 0; g < 4; g++) {       // 8 p per uint4
                const uint4 vv = vR[g];
                const unsigned int cc[4] = { vv.x, vv.y, vv.z, vv.w };
#pragma unroll
                for (int cpair = 0; cpair < 4; cpair++) {
                    const int pi = g * 4 + cpair;       // ulonglong2 index (2 p)
                    const float vlo = __uint_as_float(cc[cpair] << 16);
                    const float vhi = __uint_as_float(cc[cpair] & 0xffff0000u);
                    const ulonglong2 wa = w0[pi];
                    const ulonglong2 wb = w1p[pi];
                    const unsigned long long vl2 = pack2(vlo, vlo);
                    const unsigned long long vh2 = pack2(vhi, vhi);
                    fma2(A0, wa.x, vl2); fma2(A0, wa.y, vh2);
                    fma2(A1, wb.x, vl2); fma2(A1, wb.y, vh2);
                }
            }
            acc[0][h] = A0; acc[1][h] = A1;
        }
        __syncwarp();   // ws reused next tile (per-warp)
    }

    // ---- epilogue ----
#pragma unroll
    for (int qp = 0; qp < 2; qp++) {
#pragma unroll
        for (int h = 0; h < 4; h++) {
            float l0, l1; unpack2(lln[qp][h], l0, l1);
#pragma unroll
            for (int off = 16; off; off >>= 1) {
                l0 += __shfl_xor_sync(0xffffffffu, l0, off);
                l1 += __shfl_xor_sync(0xffffffffu, l1, off);
            }
            const int row0q = b * GG + q0 + qw + 2 * qp;
            if (lane == 0) {
                g_pm[ps][row0q * 4 + h]       = m[2 * qp][h];
                g_pl[ps][row0q * 4 + h]       = l0;
                g_pm[ps][(row0q + 1) * 4 + h] = m[2 * qp + 1][h];
                g_pl[ps][(row0q + 1) * 4 + h] = l1;
            }
            float a0, a1; unpack2(acc[qp][h], a0, a1);
            g_pacc[ps][(size_t)row0q * 128 + h * 32 + lane]       = a0;
            g_pacc[ps][(size_t)(row0q + 1) * 128 + h * 32 + lane] = a1;
        }
    }
}

// =============================================================================
// K2: combine p-split partials + output projection.
// =============================================================================
__global__ __launch_bounds__(128)
void outproj_kernel(const float* __restrict__ Wout,
                    float* __restrict__ out)
{
    __shared__ float hs[8 * 128];
    __shared__ float fc[8][4][PSPLIT];
    const int tid  = threadIdx.x;
    const int row0 = blockIdx.x * 8;

    if (tid < 32) {
        const int r = tid >> 2, h = tid & 3;
        const int idx = (row0 + r) * 4 + h;
        float mm[PSPLIT], ll[PSPLIT];
        float M = -1e30f;
#pragma unroll
        for (int p = 0; p < PSPLIT; p++) {
            mm[p] = g_pm[p][idx];
            ll[p] = g_pl[p][idx];
            M = fmaxf(M, mm[p]);
        }
        float L = 0.f, e[PSPLIT];
#pragma unroll
        for (int p = 0; p < PSPLIT; p++) {
            e[p] = __expf(mm[p] - M);
            L += ll[p] * e[p];
        }
#pragma unroll
        for (int p = 0; p < PSPLIT; p++) fc[r][h][p] = e[p] / L;
    }
    __syncthreads();

    for (int i = tid; i < 8 * 128; i += 128) {
        const int r = i >> 7, c = i & 127, h = c >> 5;
        float v = 0.f;
#pragma unroll
        for (int p = 0; p < PSPLIT; p++)
            v += g_pacc[p][(size_t)(row0 + r) * 128 + c] * fc[r][h][p];
        hs[i] = v;
    }
    __syncthreads();

    float a[8];
#pragma unroll
    for (int r = 0; r < 8; r++) a[r] = 0.f;

    for (int t = 0; t < 128; t += 4) {
        float w[4];
#pragma unroll
        for (int u = 0; u < 4; u++) w[u] = __ldg(Wout + (t + u) * 128 + tid);
#pragma unroll
        for (int u = 0; u < 4; u++)
#pragma unroll
            for (int r = 0; r < 8; r++) a[r] += hs[r * 128 + t + u] * w[u];
    }
#pragma unroll
    for (int r = 0; r < 8; r++)
        out[(size_t)(row0 + r) * 128 + tid] = a[r];
}

// =============================================================================
extern "C" void kernel_launch(void* const* d_in, const int* in_sizes, int n_in,
                              void* d_out, int out_size)
{
    const float* hin  = (const float*)d_in[0];
    const float* osa  = (const float*)d_in[1];
    const float* Wq   = (const float*)d_in[2];
    const float* Wk   = (const float*)d_in[3];
    const float* Wv   = (const float*)d_in[4];
    const float* Wout = (const float*)d_in[5];
    const float* w1   = (const float*)d_in[6];
    const float* b1   = (const float*)d_in[7];
    const float* w2   = (const float*)d_in[8];
    const float* b2   = (const float*)d_in[9];
    (void)in_sizes; (void)n_in;

    float* out = (float*)d_out;

    const int OUT_ELEMS = BB * GG * EE;
    const long long OSA_ELEMS = (long long)HH * BB * GG * GG;
    const int doCopy = ((long long)out_size >= OUT_ELEMS + OSA_ELEMS) ? 1 : 0;
    float* osaCopy = doCopy ? (out + OUT_ELEMS) : out;

    cudaFuncSetAttribute(attn_kernel,
                         cudaFuncAttributeMaxDynamicSharedMemorySize, SMEM_BYTES);

    qkv_kernel<<<BB * GG / 8, 256>>>(hin, Wq, Wk, Wv);
    attn_kernel<<<dim3(GG / TQ, BB, PSPLIT), NT, SMEM_BYTES>>>(
        osa, w1, b1, w2, b2, osaCopy, doCopy);
    outproj_kernel<<<BB * GG / 8, 128>>>(Wout, out);
}